// round 5
// baseline (speedup 1.0000x reference)
#include <cuda_runtime.h>
#include <cuda_bf16.h>
#include <math.h>

// ---------------------------------------------------------------------------
// MM_GCN: fp32 SIMT baseline
//   x = [a@Wa+ba ; v@Wv+bv ; l@Wl+bl + spk_emb[argmax(qmask)]]   [6000,200]
//   h0 = relu(x@W0+b0)
//   8x: hi = adj@h ; h = relu(theta*([hi|h0]@Wl) + (1-theta)*(0.9 hi + 0.1 h0))
//   out[i] = [xa|ha | xv|hv | xl|hl]                              [2000,1200]
// ---------------------------------------------------------------------------

#define NN     2000
#define DIA_L  100
#define DIA_B  20
#define N3     6000
#define DD     200

// scratch (no allocations allowed -> device globals)
__device__ float g_x [N3 * DD];
__device__ float g_h0[N3 * DD];
__device__ float g_h1[N3 * DD];
__device__ float g_h2[N3 * DD];
__device__ float g_hi[N3 * DD];

// ---------------------------------------------------------------------------
// Generic SGEMM, C[M,N] = op(A_cat[M,K] @ B[K,N]); N-tile 40 (200 = 5*40 exact)
//   A_cat(row,k) = k < K1 ? A[row*lda+k] : A2[row*lda + (k-K1)]
//   mode 0: C = AB (+bias if non-null)
//   mode 1: C = relu(AB + bias)
//   mode 2: C = relu(theta*AB + (1-theta)*(0.9*ehi + 0.1*eh0))   (GCNII layer)
// BM=64 BN=40 BK=16, TM=TN=4, 160 threads (16 row-groups x 10 col-groups)
// ---------------------------------------------------------------------------
__global__ __launch_bounds__(160)
void sgemm_k(const float* __restrict__ A, const float* __restrict__ A2, int K1,
             const float* __restrict__ B, const float* __restrict__ bias,
             float* __restrict__ C, int M, int N, int K, int lda, int ldb,
             int mode, float theta,
             const float* __restrict__ ehi, const float* __restrict__ eh0)
{
    __shared__ __align__(16) float As[16][68];  // stride 68 -> 16B-aligned rows
    __shared__ __align__(16) float Bs[16][40];

    const int tid = threadIdx.x;
    const int tx  = tid % 10;       // col group (4 cols)
    const int ty  = tid / 10;       // row group (4 rows)
    const int rowBase = blockIdx.y * 64;
    const int colBase = blockIdx.x * 40;

    float acc[4][4] = {};

    for (int k0 = 0; k0 < K; k0 += 16) {
        // load A tile [64 x 16] (1024 elems / 160 threads)
        #pragma unroll
        for (int it = 0; it < 7; it++) {
            int idx = tid + it * 160;
            if (idx < 64 * 16) {
                int m = idx >> 4, k = idx & 15;
                int row = rowBase + m, kk = k0 + k;
                float v = 0.f;
                if (row < M && kk < K)
                    v = (kk < K1) ? A [(long long)row * lda + kk]
                                  : A2[(long long)row * lda + (kk - K1)];
                As[k][m] = v;
            }
        }
        // load B tile [16 x 40] (640 elems / 160 threads)
        #pragma unroll
        for (int it = 0; it < 4; it++) {
            int idx = tid + it * 160;
            int k = idx / 40, n = idx % 40;
            int kk = k0 + k, col = colBase + n;
            Bs[k][n] = (kk < K && col < N) ? B[(long long)kk * ldb + col] : 0.f;
        }
        __syncthreads();

        #pragma unroll
        for (int k = 0; k < 16; k++) {
            float4 av = *reinterpret_cast<const float4*>(&As[k][ty * 4]);
            float4 bv = *reinterpret_cast<const float4*>(&Bs[k][tx * 4]);
            float a4[4] = {av.x, av.y, av.z, av.w};
            float b4[4] = {bv.x, bv.y, bv.z, bv.w};
            #pragma unroll
            for (int i = 0; i < 4; i++)
                #pragma unroll
                for (int j = 0; j < 4; j++)
                    acc[i][j] = fmaf(a4[i], b4[j], acc[i][j]);
        }
        __syncthreads();
    }

    const float omt = 1.f - theta;
    #pragma unroll
    for (int i = 0; i < 4; i++) {
        int row = rowBase + ty * 4 + i;
        if (row >= M) continue;
        #pragma unroll
        for (int j = 0; j < 4; j++) {
            int col = colBase + tx * 4 + j;
            if (col >= N) continue;
            long long o = (long long)row * N + col;
            float v = acc[i][j];
            if (mode == 2) {
                v = theta * v + omt * (0.9f * ehi[o] + 0.1f * eh0[o]);
                v = fmaxf(v, 0.f);
            } else {
                if (bias) v += bias[col];
                if (mode == 1) v = fmaxf(v, 0.f);
            }
            C[o] = v;
        }
    }
}

// add speaker embedding to the 'l' modality rows of x
__global__ void spk_add_k(float* __restrict__ x_l,
                          const float* __restrict__ qmask,
                          const float* __restrict__ spk_emb)
{
    int idx = blockIdx.x * blockDim.x + threadIdx.x;
    if (idx >= NN * DD) return;
    int i = idx / DD, c = idx % DD;
    int t = i % DIA_L, b = i / DIA_L;           // qcat[b*L+t] = qmask[t,b]
    const float* q = qmask + ((long long)t * DIA_B + b) * 2;
    int s = (q[1] > q[0]) ? 1 : 0;              // argmax, tie -> 0
    x_l[idx] += spk_emb[s * DD + c];
}

// out[i, m*400 + {0..199}] = x[m*2000+i], out[i, m*400 + {200..399}] = h[m*2000+i]
__global__ void assemble_k(const float* __restrict__ x,
                           const float* __restrict__ h,
                           float* __restrict__ out)
{
    int idx = blockIdx.x * blockDim.x + threadIdx.x;
    if (idx >= NN * 1200) return;
    int i = idx / 1200, r = idx % 1200;
    int m = r / 400, c = r % 400;
    const float* src = (c < 200) ? x : h;
    out[idx] = src[((long long)(m * NN + i)) * DD + (c % 200)];
}

static void gemm(const float* A, const float* A2, int K1,
                 const float* B, const float* bias, float* C,
                 int M, int N, int K, int lda, int ldb,
                 int mode, float theta, const float* ehi, const float* eh0)
{
    dim3 grid((N + 39) / 40, (M + 63) / 64);
    sgemm_k<<<grid, 160>>>(A, A2, K1, B, bias, C, M, N, K, lda, ldb,
                           mode, theta, ehi, eh0);
}

extern "C" void kernel_launch(void* const* d_in, const int* in_sizes, int n_in,
                              void* d_out, int out_size)
{
    const float* a       = (const float*)d_in[0];   // [2000,300]
    const float* v       = (const float*)d_in[1];   // [2000,342]
    const float* l       = (const float*)d_in[2];   // [2000,1024]
    const float* qmask   = (const float*)d_in[3];   // [100,20,2]
    const float* adj     = (const float*)d_in[4];   // [6000,6000]
    const float* Wa      = (const float*)d_in[5];   // [300,200]
    const float* ba      = (const float*)d_in[6];
    const float* Wv      = (const float*)d_in[7];   // [342,200]
    const float* bv      = (const float*)d_in[8];
    const float* Wl      = (const float*)d_in[9];   // [1024,200]
    const float* bl      = (const float*)d_in[10];
    const float* spk_emb = (const float*)d_in[11];  // [2,200]
    const float* W0      = (const float*)d_in[12];  // [200,200]
    const float* b0      = (const float*)d_in[13];
    const float* convW   = (const float*)d_in[14];  // [8,400,200]
    (void)in_sizes; (void)n_in;                     // dia_len hardcoded (100)

    float *x, *h0, *h1, *h2, *hi;
    cudaGetSymbolAddress((void**)&x,  g_x);
    cudaGetSymbolAddress((void**)&h0, g_h0);
    cudaGetSymbolAddress((void**)&h1, g_h1);
    cudaGetSymbolAddress((void**)&h2, g_h2);
    cudaGetSymbolAddress((void**)&hi, g_hi);

    // modality projections into x = [a_proj ; v_proj ; l_proj]
    gemm(a, a, 300,  Wa, ba, x,               2000, DD, 300,  300,  DD, 0, 0.f, nullptr, nullptr);
    gemm(v, v, 342,  Wv, bv, x + 2000 * DD,   2000, DD, 342,  342,  DD, 0, 0.f, nullptr, nullptr);
    gemm(l, l, 1024, Wl, bl, x + 4000 * DD,   2000, DD, 1024, 1024, DD, 0, 0.f, nullptr, nullptr);
    spk_add_k<<<(NN * DD + 255) / 256, 256>>>(x + 4000 * DD, qmask, spk_emb);

    // h0 = relu(x @ W0 + b0)
    gemm(x, x, DD, W0, b0, h0, N3, DD, DD, DD, DD, 1, 0.f, nullptr, nullptr);

    // 8 GCNII layers
    const float* hcur = h0;
    float* hnext = h1;
    for (int layer = 0; layer < 8; layer++) {
        float theta = logf(0.5f / (float)(layer + 1) + 1.0f);
        // hi = adj @ h          (M=6000, N=200, K=6000)
        gemm(adj, adj, N3, hcur, nullptr, hi, N3, DD, N3, N3, DD, 0, 0.f, nullptr, nullptr);
        // h = relu(theta * ([hi|h0] @ W_l) + (1-theta)*(0.9 hi + 0.1 h0))
        gemm(hi, h0, DD, convW + (long long)layer * 400 * DD, nullptr, hnext,
             N3, DD, 400, DD, DD, 2, theta, hi, h0);
        hcur  = hnext;
        hnext = (hnext == h1) ? h2 : h1;
    }

    // fuse per-modality [x|h] chunks along features
    assemble_k<<<(NN * 1200 + 255) / 256, 256>>>(x, hcur, (float*)d_out);
    (void)out_size;
}

// round 8
// speedup vs baseline: 2.4654x; 2.4654x over previous
#include <cuda_runtime.h>
#include <cuda_bf16.h>
#include <math.h>
#include <stdint.h>

// ---------------------------------------------------------------------------
// MM_GCN — round 5: TF32 tensor-core path for adj@h and [hi|h0]@W
// ---------------------------------------------------------------------------
#define NN     2000
#define DIA_L  100
#define DIA_B  20
#define N3     6000
#define DD     200

// scratch (no allocations allowed -> device globals)
__device__ float g_x  [N3 * DD];
__device__ float g_h0 [N3 * DD];
__device__ float g_h1 [N3 * DD];
__device__ float g_h2 [N3 * DD];
__device__ float g_hi [N3 * DD];
// tf32-rounded copies
__device__ float g_adjc[(long long)N3 * N3];   // 144 MB
__device__ float g_hc  [N3 * DD];
__device__ float g_hic [N3 * DD];
__device__ float g_h0c [N3 * DD];
__device__ float g_cwc [8 * 400 * DD];

// ---------------------------------------------------------------------------
// round-to-nearest tf32 conversion (vectorized)
// ---------------------------------------------------------------------------
__device__ __forceinline__ float to_tf32(float x) {
    uint32_t r;
    asm("cvt.rna.tf32.f32 %0, %1;" : "=r"(r) : "f"(x));
    return __uint_as_float(r);
}

__global__ void cvt_tf32_k(const float* __restrict__ in, float* __restrict__ out, int n4) {
    int i = blockIdx.x * blockDim.x + threadIdx.x;
    if (i >= n4) return;
    float4 v = reinterpret_cast<const float4*>(in)[i];
    v.x = to_tf32(v.x); v.y = to_tf32(v.y); v.z = to_tf32(v.z); v.w = to_tf32(v.w);
    reinterpret_cast<float4*>(out)[i] = v;
}

// ---------------------------------------------------------------------------
// TF32 tensor-core GEMM: C[M,200] = op(A_cat[M,K] @ B[K,200])
//   A_cat(row,k) = k < K1 ? A[row*lda+k] : A2[row*lda+(k-K1)]   (inputs tf32-rounded)
//   mode 0: C = AB
//   mode 2: C = relu(theta*AB + (1-theta)*(0.9*ehi + 0.1*eh0))  (ehi/eh0 fp32 exact)
// BM=128 BN=40 BK=32, 4 warps, warp tile 32x40 (2 x m16 by 5 x n8), mma m16n8k8
// ---------------------------------------------------------------------------
__global__ __launch_bounds__(128)
void tf32_gemm_k(const float* __restrict__ A, const float* __restrict__ A2,
                 int K1, int lda,
                 const float* __restrict__ B, int ldb,
                 float* __restrict__ C, int M, int K,
                 int mode, float theta,
                 const float* __restrict__ ehi, const float* __restrict__ eh0)
{
    __shared__ __align__(16) float As[128][36];  // m-major; stride 36 -> conflict-free frags
    __shared__ __align__(16) float Bs[32][40];   // k-major; 40 mod 32 = 8 -> conflict-free

    const int tid  = threadIdx.x;
    const int lane = tid & 31, warp = tid >> 5;
    const int rowBase = blockIdx.y * 128;
    const int colBase = blockIdx.x * 40;
    const int mbase   = warp * 32;
    const int g  = lane >> 2;      // group id (0..7)
    const int t4 = lane & 3;       // thread in group (0..3)

    float acc[2][5][4];
    #pragma unroll
    for (int mi = 0; mi < 2; mi++)
        #pragma unroll
        for (int nt = 0; nt < 5; nt++)
            #pragma unroll
            for (int q = 0; q < 4; q++) acc[mi][nt][q] = 0.f;

    const int arow = rowBase + tid;  // one A row per thread

    for (int k0 = 0; k0 < K; k0 += 32) {
        // --- load A tile [128 x 32], one row (32 floats = 8 float4) per thread
        #pragma unroll
        for (int c = 0; c < 8; c++) {
            int kk = k0 + c * 4;
            float4 v = make_float4(0.f, 0.f, 0.f, 0.f);
            if (arow < M && kk < K) {
                const float* p = (kk < K1)
                    ? A  + (long long)arow * lda + kk
                    : A2 + (long long)arow * lda + (kk - K1);
                v = *reinterpret_cast<const float4*>(p);
            }
            *reinterpret_cast<float4*>(&As[tid][c * 4]) = v;
        }
        // --- load B tile [32 x 40] = 320 float4
        #pragma unroll
        for (int i = tid; i < 320; i += 128) {
            int bk = i / 10, nq = i % 10;
            int kk = k0 + bk;
            float4 v = make_float4(0.f, 0.f, 0.f, 0.f);
            if (kk < K)
                v = *reinterpret_cast<const float4*>(B + (long long)kk * ldb + colBase + nq * 4);
            *reinterpret_cast<float4*>(&Bs[bk][nq * 4]) = v;
        }
        __syncthreads();

        #pragma unroll
        for (int ks = 0; ks < 32; ks += 8) {
            uint32_t a[2][4], b[5][2];
            #pragma unroll
            for (int mi = 0; mi < 2; mi++) {
                int r = mbase + mi * 16 + g;
                a[mi][0] = __float_as_uint(As[r    ][ks + t4]);
                a[mi][1] = __float_as_uint(As[r + 8][ks + t4]);
                a[mi][2] = __float_as_uint(As[r    ][ks + 4 + t4]);
                a[mi][3] = __float_as_uint(As[r + 8][ks + 4 + t4]);
            }
            #pragma unroll
            for (int nt = 0; nt < 5; nt++) {
                b[nt][0] = __float_as_uint(Bs[ks + t4    ][nt * 8 + g]);
                b[nt][1] = __float_as_uint(Bs[ks + 4 + t4][nt * 8 + g]);
            }
            #pragma unroll
            for (int mi = 0; mi < 2; mi++)
                #pragma unroll
                for (int nt = 0; nt < 5; nt++)
                    asm volatile(
                        "mma.sync.aligned.m16n8k8.row.col.f32.tf32.tf32.f32 "
                        "{%0,%1,%2,%3}, {%4,%5,%6,%7}, {%8,%9}, {%0,%1,%2,%3};\n"
                        : "+f"(acc[mi][nt][0]), "+f"(acc[mi][nt][1]),
                          "+f"(acc[mi][nt][2]), "+f"(acc[mi][nt][3])
                        : "r"(a[mi][0]), "r"(a[mi][1]), "r"(a[mi][2]), "r"(a[mi][3]),
                          "r"(b[nt][0]), "r"(b[nt][1]));
        }
        __syncthreads();
    }

    // --- epilogue: c0,c1 -> (row=g, col=2t,2t+1); c2,c3 -> row=g+8
    const float omt = 1.f - theta;
    #pragma unroll
    for (int mi = 0; mi < 2; mi++) {
        #pragma unroll
        for (int half = 0; half < 2; half++) {
            int row = rowBase + mbase + mi * 16 + half * 8 + g;
            if (row >= M) continue;
            #pragma unroll
            for (int nt = 0; nt < 5; nt++) {
                int col = colBase + nt * 8 + t4 * 2;
                long long o = (long long)row * DD + col;
                float v0 = acc[mi][nt][half * 2 + 0];
                float v1 = acc[mi][nt][half * 2 + 1];
                if (mode == 2) {
                    v0 = fmaxf(theta * v0 + omt * (0.9f * ehi[o]     + 0.1f * eh0[o]),     0.f);
                    v1 = fmaxf(theta * v1 + omt * (0.9f * ehi[o + 1] + 0.1f * eh0[o + 1]), 0.f);
                }
                *reinterpret_cast<float2*>(C + o) = make_float2(v0, v1);
            }
        }
    }
}

// ---------------------------------------------------------------------------
// fp32 SIMT GEMM (kept for projections + h0; x must stay bit-accurate-ish)
// ---------------------------------------------------------------------------
__global__ __launch_bounds__(160)
void sgemm_k(const float* __restrict__ A, const float* __restrict__ A2, int K1,
             const float* __restrict__ B, const float* __restrict__ bias,
             float* __restrict__ C, int M, int N, int K, int lda, int ldb,
             int mode)
{
    __shared__ __align__(16) float As[16][68];
    __shared__ __align__(16) float Bs[16][40];

    const int tid = threadIdx.x;
    const int tx  = tid % 10;
    const int ty  = tid / 10;
    const int rowBase = blockIdx.y * 64;
    const int colBase = blockIdx.x * 40;

    float acc[4][4] = {};

    for (int k0 = 0; k0 < K; k0 += 16) {
        #pragma unroll
        for (int it = 0; it < 7; it++) {
            int idx = tid + it * 160;
            if (idx < 64 * 16) {
                int m = idx >> 4, k = idx & 15;
                int row = rowBase + m, kk = k0 + k;
                float v = 0.f;
                if (row < M && kk < K)
                    v = (kk < K1) ? A [(long long)row * lda + kk]
                                  : A2[(long long)row * lda + (kk - K1)];
                As[k][m] = v;
            }
        }
        #pragma unroll
        for (int it = 0; it < 4; it++) {
            int idx = tid + it * 160;
            int k = idx / 40, n = idx % 40;
            int kk = k0 + k, col = colBase + n;
            Bs[k][n] = (kk < K && col < N) ? B[(long long)kk * ldb + col] : 0.f;
        }
        __syncthreads();

        #pragma unroll
        for (int k = 0; k < 16; k++) {
            float4 av = *reinterpret_cast<const float4*>(&As[k][ty * 4]);
            float4 bv = *reinterpret_cast<const float4*>(&Bs[k][tx * 4]);
            float a4[4] = {av.x, av.y, av.z, av.w};
            float b4[4] = {bv.x, bv.y, bv.z, bv.w};
            #pragma unroll
            for (int i = 0; i < 4; i++)
                #pragma unroll
                for (int j = 0; j < 4; j++)
                    acc[i][j] = fmaf(a4[i], b4[j], acc[i][j]);
        }
        __syncthreads();
    }

    #pragma unroll
    for (int i = 0; i < 4; i++) {
        int row = rowBase + ty * 4 + i;
        if (row >= M) continue;
        #pragma unroll
        for (int j = 0; j < 4; j++) {
            int col = colBase + tx * 4 + j;
            if (col >= N) continue;
            float v = acc[i][j];
            if (bias) v += bias[col];
            if (mode == 1) v = fmaxf(v, 0.f);
            C[(long long)row * N + col] = v;
        }
    }
}

__global__ void spk_add_k(float* __restrict__ x_l,
                          const float* __restrict__ qmask,
                          const float* __restrict__ spk_emb)
{
    int idx = blockIdx.x * blockDim.x + threadIdx.x;
    if (idx >= NN * DD) return;
    int i = idx / DD, c = idx % DD;
    int t = i % DIA_L, b = i / DIA_L;
    const float* q = qmask + ((long long)t * DIA_B + b) * 2;
    int s = (q[1] > q[0]) ? 1 : 0;
    x_l[idx] += spk_emb[s * DD + c];
}

__global__ void assemble_k(const float* __restrict__ x,
                           const float* __restrict__ h,
                           float* __restrict__ out)
{
    int idx = blockIdx.x * blockDim.x + threadIdx.x;
    if (idx >= NN * 1200) return;
    int i = idx / 1200, r = idx % 1200;
    int m = r / 400, c = r % 400;
    const float* src = (c < 200) ? x : h;
    out[idx] = src[((long long)(m * NN + i)) * DD + (c % 200)];
}

static void gemm(const float* A, const float* A2, int K1,
                 const float* B, const float* bias, float* C,
                 int M, int N, int K, int lda, int ldb, int mode)
{
    dim3 grid((N + 39) / 40, (M + 63) / 64);
    sgemm_k<<<grid, 160>>>(A, A2, K1, B, bias, C, M, N, K, lda, ldb, mode);
}

static void tgemm(const float* A, const float* A2, int K1, int lda,
                  const float* B, int ldb, float* C, int M, int K,
                  int mode, float theta, const float* ehi, const float* eh0)
{
    dim3 grid(5, (M + 127) / 128);    // x-fast: 5 col-blocks share adj rows in L2
    tf32_gemm_k<<<grid, 128>>>(A, A2, K1, lda, B, ldb, C, M, K, mode, theta, ehi, eh0);
}

static void cvt(const float* in, float* out, long long n)
{
    int n4 = (int)(n / 4);
    cvt_tf32_k<<<(n4 + 255) / 256, 256>>>(in, out, n4);
}

extern "C" void kernel_launch(void* const* d_in, const int* in_sizes, int n_in,
                              void* d_out, int out_size)
{
    const float* a       = (const float*)d_in[0];
    const float* v       = (const float*)d_in[1];
    const float* l       = (const float*)d_in[2];
    const float* qmask   = (const float*)d_in[3];
    const float* adj     = (const float*)d_in[4];
    const float* Wa      = (const float*)d_in[5];
    const float* ba      = (const float*)d_in[6];
    const float* Wv      = (const float*)d_in[7];
    const float* bv      = (const float*)d_in[8];
    const float* Wl      = (const float*)d_in[9];
    const float* bl      = (const float*)d_in[10];
    const float* spk_emb = (const float*)d_in[11];
    const float* W0      = (const float*)d_in[12];
    const float* b0      = (const float*)d_in[13];
    const float* convW   = (const float*)d_in[14];
    (void)in_sizes; (void)n_in;

    float *x, *h0, *h1, *h2, *hi, *adjc, *hc, *hic, *h0c, *cwc;
    cudaGetSymbolAddress((void**)&x,    g_x);
    cudaGetSymbolAddress((void**)&h0,   g_h0);
    cudaGetSymbolAddress((void**)&h1,   g_h1);
    cudaGetSymbolAddress((void**)&h2,   g_h2);
    cudaGetSymbolAddress((void**)&hi,   g_hi);
    cudaGetSymbolAddress((void**)&adjc, g_adjc);
    cudaGetSymbolAddress((void**)&hc,   g_hc);
    cudaGetSymbolAddress((void**)&hic,  g_hic);
    cudaGetSymbolAddress((void**)&h0c,  g_h0c);
    cudaGetSymbolAddress((void**)&cwc,  g_cwc);

    // tf32-round the static operands (adj once; convW once)
    cvt(adj,   adjc, (long long)N3 * N3);
    cvt(convW, cwc,  8LL * 400 * DD);

    // modality projections into x (fp32 exact — x is part of the output)
    gemm(a, a, 300,  Wa, ba, x,             2000, DD, 300,  300,  DD, 0);
    gemm(v, v, 342,  Wv, bv, x + 2000 * DD, 2000, DD, 342,  342,  DD, 0);
    gemm(l, l, 1024, Wl, bl, x + 4000 * DD, 2000, DD, 1024, 1024, DD, 0);
    spk_add_k<<<(NN * DD + 255) / 256, 256>>>(x + 4000 * DD, qmask, spk_emb);

    // h0 = relu(x @ W0 + b0) (fp32)
    gemm(x, x, DD, W0, b0, h0, N3, DD, DD, DD, DD, 1);
    cvt(h0, h0c, (long long)N3 * DD);

    // 8 GCNII layers, tensor-core path
    const float* hcur = h0;
    float* hnext = h1;
    for (int layer = 0; layer < 8; layer++) {
        float theta = logf(0.5f / (float)(layer + 1) + 1.0f);
        cvt(hcur, hc, (long long)N3 * DD);
        // hi = adj @ h
        tgemm(adjc, adjc, N3, N3, hc, DD, hi, N3, N3, 0, 0.f, nullptr, nullptr);
        cvt(hi, hic, (long long)N3 * DD);
        // h = relu(theta*([hi|h0]@W) + (1-theta)*(0.9 hi + 0.1 h0))
        tgemm(hic, h0c, DD, DD, cwc + (long long)layer * 400 * DD, DD,
              hnext, N3, 400, 2, theta, hi, h0);
        hcur  = hnext;
        hnext = (hnext == h1) ? h2 : h1;
    }

    assemble_k<<<(NN * 1200 + 255) / 256, 256>>>(x, hcur, (float*)d_out);
    (void)out_size;
}